// round 12
// baseline (speedup 1.0000x reference)
#include <cuda_runtime.h>
#include <math.h>

#define NN 50000
#define TT 1000
#define KL 5
#define KR 15
#define NC 5
#define PI_F 3.14159265358979323846f
#define PREG 148
#define PRETHR 512
#define GRIDF 592
#define SUBMAX 29

typedef unsigned long long ull;

__device__ __forceinline__ ull pk2(float lo, float hi) {
    ull r; asm("mov.b64 %0,{%1,%2};" : "=l"(r) : "f"(lo), "f"(hi)); return r;
}
__device__ __forceinline__ float2 upk2(ull v) {
    float2 f; asm("mov.b64 {%0,%1},%2;" : "=f"(f.x), "=f"(f.y) : "l"(v)); return f;
}
__device__ __forceinline__ ull ffma2(ull a, ull b, ull c) {
    ull d; asm("fma.rn.f32x2 %0,%1,%2,%3;" : "=l"(d) : "l"(a), "l"(b), "l"(c)); return d;
}
__device__ __forceinline__ ull fmul2(ull a, ull b) {
    ull d; asm("mul.rn.f32x2 %0,%1,%2;" : "=l"(d) : "l"(a), "l"(b)); return d;
}

// packed 64B node rows: [float4 amp][float4 cos][float4 sin][pad]
__device__ float4 g_nd[NN * 4];
// per-block partial cluster sums
__device__ float g_partial[PREG * 65];
// finalized cluster stats: [0..19] meanAmp, [20..39] circPhase, [40..44] big
__device__ float g_cmeans[48];
__device__ unsigned g_arr;  // arrival counter; reset by last block each launch

// ---------------------------------------------------------------------------
// Stage 1 (unchanged from R11, verified): node table + cluster stats.
// ---------------------------------------------------------------------------
__global__ __launch_bounds__(PRETHR) void k_pre(const float4* __restrict__ amp,
                                                const float4* __restrict__ ph,
                                                const int* __restrict__ lab) {
    __shared__ float s_part[64 * 65];
    __shared__ float s_cl[65];
    __shared__ unsigned s_last;
    int tid = threadIdx.x;
    int wid = tid >> 5, lane = tid & 31;
    int n = blockIdx.x * PRETHR + tid;

    float v[13];
    int c = -1;
    if (n < NN) {
        float4 p = ph[n];
        float4 cs, sn;
        __sincosf(p.x, &sn.x, &cs.x);
        __sincosf(p.y, &sn.y, &cs.y);
        __sincosf(p.z, &sn.z, &cs.z);
        __sincosf(p.w, &sn.w, &cs.w);
        float4 a = amp[n];
        g_nd[n * 4 + 0] = a;
        g_nd[n * 4 + 1] = cs;
        g_nd[n * 4 + 2] = sn;
        c = lab[n];
        v[0] = 1.f;
        v[1] = a.x;  v[2] = a.y;  v[3] = a.z;  v[4] = a.w;
        v[5] = cs.x; v[6] = cs.y; v[7] = cs.z; v[8] = cs.w;
        v[9] = sn.x; v[10] = sn.y; v[11] = sn.z; v[12] = sn.w;
    } else {
        #pragma unroll
        for (int i = 0; i < 13; i++) v[i] = 0.f;
    }

    #pragma unroll
    for (int cc = 0; cc < NC; cc++) {
        #pragma unroll
        for (int i = 0; i < 13; i++) {
            float x = (c == cc) ? v[i] : 0.f;
            x += __shfl_xor_sync(0xffffffffu, x, 16);
            x += __shfl_xor_sync(0xffffffffu, x, 8);
            x += __shfl_xor_sync(0xffffffffu, x, 4);
            if (lane < 4) s_part[(wid * 4 + lane) * 65 + cc * 13 + i] = x;
        }
    }
    __syncthreads();
    if (tid < 65) {
        float s = 0.f;
        #pragma unroll
        for (int w = 0; w < 64; w++) s += s_part[w * 65 + tid];
        g_partial[blockIdx.x * 65 + tid] = s;
    }
    __threadfence();
    __syncthreads();
    if (tid == 0) {
        unsigned o = atomicAdd(&g_arr, 1u);
        s_last = (o == PREG - 1) ? 1u : 0u;
    }
    __syncthreads();
    if (s_last) {
        __threadfence();
        if (tid < 65) {
            float s = 0.f;
            for (int r = 0; r < PREG; r++) s += g_partial[r * 65 + tid];
            s_cl[tid] = s;
        }
        __syncthreads();
        if (tid < 20) {
            int cc = tid >> 2, i = tid & 3;
            float cnt = s_cl[cc * 13];
            g_cmeans[tid]      = s_cl[cc * 13 + 1 + i] / fmaxf(cnt, 1.f);
            g_cmeans[20 + tid] = atan2f(s_cl[cc * 13 + 9 + i], s_cl[cc * 13 + 5 + i]);
            if (i == 0) g_cmeans[40 + cc] = (cnt > 1.f) ? 1.f : 0.f;
        }
        if (tid == 0) g_arr = 0u;
    }
}

// ---------------------------------------------------------------------------
// WORK-group unit: gather + coef for one sub-slab. Called by threads 128..255
// (tid2 = 0..127). Internal ordering via named barrier 1 (128 threads).
// ---------------------------------------------------------------------------
__device__ __forceinline__ void gather_coef(
    int tid2, int gbase, int cnt,
    const ulonglong2* __restrict__ ndA,
    const float* __restrict__ co, const float* __restrict__ lt,
    const float* __restrict__ amp, const float* __restrict__ ph,
    const float* __restrict__ lw, const float* __restrict__ rw,
    const int* __restrict__ li, const int* __restrict__ ri,
    const int* __restrict__ lab,
    const float* s_cm, ull* s_pp, ulonglong2* s_cpO)
{
    int node = -1, chunk = 0;
    if (tid2 < 3 * cnt) { chunk = tid2 / cnt; node = tid2 - chunk * cnt; }

    ull la01 = 0, la23 = 0, lc01 = 0, lc23 = 0, ls01 = 0, ls23 = 0;
    float4 a4 = make_float4(0.f, 0.f, 0.f, 0.f), p4 = a4;
    float cov = 0.f, ltv = 0.f;
    int c = 0;

    if (node >= 0) {
        int gn = gbase + node;
        if (chunk == 0) {
            a4 = ((const float4*)amp)[gn];
            p4 = ((const float4*)ph)[gn];
            cov = co[gn]; ltv = lt[gn]; c = lab[gn];
            #pragma unroll
            for (int k = 0; k < KL; k++) {
                int j = li[gn * KL + k];
                float w = lw[gn * KL + k];
                ull wP = pk2(w, w);
                ulonglong2 aj = ndA[j * 4 + 0];
                ulonglong2 cj = ndA[j * 4 + 1];
                ulonglong2 sj = ndA[j * 4 + 2];
                la01 = ffma2(aj.x, wP, la01); la23 = ffma2(aj.y, wP, la23);
                lc01 = ffma2(cj.x, wP, lc01); lc23 = ffma2(cj.y, wP, lc23);
                ls01 = ffma2(sj.x, wP, ls01); ls23 = ffma2(sj.y, wP, ls23);
            }
        } else {
            int kb = (chunk == 1) ? 0 : 8;
            int ke = (chunk == 1) ? 8 : KR;
            ull r0 = 0, r1 = 0, r2 = 0, r3 = 0, r4 = 0, r5 = 0;
            for (int k = kb; k < ke; k++) {
                int j = ri[(gbase + node) * KR + k];
                float w = rw[(gbase + node) * KR + k];
                ull wP = pk2(w, w);
                ulonglong2 aj = ndA[j * 4 + 0];
                ulonglong2 cj = ndA[j * 4 + 1];
                ulonglong2 sj = ndA[j * 4 + 2];
                r0 = ffma2(aj.x, wP, r0); r1 = ffma2(aj.y, wP, r1);
                r2 = ffma2(cj.x, wP, r2); r3 = ffma2(cj.y, wP, r3);
                r4 = ffma2(sj.x, wP, r4); r5 = ffma2(sj.y, wP, r5);
            }
            ull* dst = &s_pp[node * 12 + (chunk - 1) * 6];
            dst[0] = r0; dst[1] = r1; dst[2] = r2;
            dst[3] = r3; dst[4] = r4; dst[5] = r5;
        }
    }
    asm volatile("bar.sync 1, 128;" ::: "memory");

    if (node >= 0 && chunk == 0) {
        float ra[4], rc[4], rs[4];
        {
            const ull* p1 = &s_pp[node * 12];
            const ull* p2 = p1 + 6;
            float2 x, y;
            x = upk2(p1[0]); y = upk2(p2[0]); ra[0] = x.x + y.x; ra[1] = x.y + y.y;
            x = upk2(p1[1]); y = upk2(p2[1]); ra[2] = x.x + y.x; ra[3] = x.y + y.y;
            x = upk2(p1[2]); y = upk2(p2[2]); rc[0] = x.x + y.x; rc[1] = x.y + y.y;
            x = upk2(p1[3]); y = upk2(p2[3]); rc[2] = x.x + y.x; rc[3] = x.y + y.y;
            x = upk2(p1[4]); y = upk2(p2[4]); rs[0] = x.x + y.x; rs[1] = x.y + y.y;
            x = upk2(p1[5]); y = upk2(p2[5]); rs[2] = x.x + y.x; rs[3] = x.y + y.y;
        }
        float la[4], lc[4], ls[4];
        float2 t;
        t = upk2(la01); la[0] = t.x; la[1] = t.y;  t = upk2(la23); la[2] = t.x; la[3] = t.y;
        t = upk2(lc01); lc[0] = t.x; lc[1] = t.y;  t = upk2(lc23); lc[2] = t.x; lc[3] = t.y;
        t = upk2(ls01); ls[0] = t.x; ls[1] = t.y;  t = upk2(ls23); ls[2] = t.x; ls[3] = t.y;

        bool big = s_cm[40 + c] > 0.5f;
        float aP[4] = {a4.x, a4.y, a4.z, a4.w};
        float pP[4] = {p4.x, p4.y, p4.z, p4.w};
        float av[4], bv[4];
        #pragma unroll
        for (int i = 0; i < 4; i++) {
            float campU = big ? s_cm[c * 4 + i] : aP[i];
            // combined = 0.5*local + 0.3*(0.7*regional_sum) + 0.2*cluster
            float ampO = 0.7f * aP[i] + 0.3f * (0.5f * la[i] + 0.21f * ra[i] + 0.2f * campU);
            float cphU = big ? s_cm[20 + c * 4 + i] : pP[i];
            float phL = atan2f(ls[i], lc[i]);
            float phR = atan2f(rs[i], rc[i]);
            float phO = 0.7f * pP[i] + 0.3f * (0.5f * phL + 0.3f * phR + 0.2f * cphU);
            float s, cc2;
            __sincosf(phO, &s, &cc2);
            av[i] = ampO * cc2;
            bv[i] = ampO * s;
        }
        ull* q = (ull*)&s_cpO[node * 5];
        q[0] = pk2(cov, cov);     q[1] = pk2(ltv, ltv);
        q[2] = pk2(av[0], av[0]); q[3] = pk2(av[1], av[1]);
        q[4] = pk2(av[2], av[2]); q[5] = pk2(av[3], av[3]);
        q[6] = pk2(bv[0], bv[0]); q[7] = pk2(bv[1], bv[1]);
        q[8] = pk2(bv[2], bv[2]); q[9] = pk2(bv[3], bv[3]);
    }
}

// ---------------------------------------------------------------------------
// Stage 2: warp-specialized pipeline.
//   warps 0-3 (FILL, 125 active threads x 8 t in 2 coalesced halves)
//   warps 4-7 (WORK, gather+coef for the NEXT sub-slab)
// 3 sub-slabs; stage boundaries = __syncthreads (both groups, same count).
// Output stores use __stcs (evict-first) so 200MB of writes don't evict the
// 3.2MB g_nd table that overlapped gathers depend on.
// ---------------------------------------------------------------------------
__global__ __launch_bounds__(256, 4) void k_fused(const float* __restrict__ tv,
                                                  const float* __restrict__ co,
                                                  const float* __restrict__ lt,
                                                  const float* __restrict__ amp,
                                                  const float* __restrict__ ph,
                                                  const float* __restrict__ lw,
                                                  const float* __restrict__ rw,
                                                  const int* __restrict__ li,
                                                  const int* __restrict__ ri,
                                                  const int* __restrict__ lab,
                                                  float* __restrict__ out) {
    __shared__ float2 s_trig[TT];               // (sin,cos)(pi*t)
    __shared__ ull s_pp[SUBMAX * 12];
    __shared__ ulonglong2 s_cpA[SUBMAX * 5];
    __shared__ ulonglong2 s_cpB[SUBMAX * 5];
    __shared__ float s_cm[48];
    int tid = threadIdx.x;
    int start = (int)(((long long)blockIdx.x * NN) / GRIDF);
    int end   = (int)(((long long)(blockIdx.x + 1) * NN) / GRIDF);
    int nn = end - start;
    int bb[4] = {0, nn / 3, (2 * nn) / 3, nn};

    const ulonglong2* ndA = (const ulonglong2*)g_nd;

    if (tid < 128) {
        // FILL group prologue: build full trig table (8 sincosf/thread)
        for (int i = tid; i < TT; i += 128) {
            float t = tv[i];
            float s, cq;
            sincosf(PI_F * t, &s, &cq);
            s_trig[i] = make_float2(s, cq);
        }
    } else {
        int tid2 = tid - 128;
        if (tid2 < 48) s_cm[tid2] = g_cmeans[tid2];
        gather_coef(tid2, start + bb[0], bb[1] - bb[0], ndA, co, lt, amp, ph,
                    lw, rw, li, ri, lab, s_cm, s_pp, s_cpA);
    }

    for (int s = 0; s < 3; s++) {
        __syncthreads();   // s_cp[s&1] ready; s_pp free for next gather
        if (tid < 128) {
            // FILL sub-slab s
            int cnt = bb[s + 1] - bb[s];
            int gbase = start + bb[s];
            const ulonglong2* buf = (s & 1) ? s_cpB : s_cpA;
            if (tid < 125) {
                #pragma unroll 1
                for (int h = 0; h < 2; h++) {
                    int t0 = h * 500 + tid * 4;
                    float4 tvv = ((const float4*)tv)[h * 125 + tid];
                    ull T01 = pk2(tvv.x, tvv.y);
                    ull T23 = pk2(tvv.z, tvv.w);
                    float2 q0 = s_trig[t0], q1 = s_trig[t0 + 1];
                    float2 q2 = s_trig[t0 + 2], q3 = s_trig[t0 + 3];
                    ull TWO = pk2(2.f, 2.f), NTWO = pk2(-2.f, -2.f), ONE = pk2(1.f, 1.f);
                    ull S01[4], C01[4], S23[4], C23[4];
                    S01[3] = pk2(q0.x, q1.x); C01[3] = pk2(q0.y, q1.y);
                    S23[3] = pk2(q2.x, q3.x); C23[3] = pk2(q2.y, q3.y);
                    #pragma unroll
                    for (int lv = 3; lv > 0; lv--) {
                        S01[lv-1] = fmul2(fmul2(TWO, S01[lv]), C01[lv]);
                        C01[lv-1] = ffma2(fmul2(NTWO, S01[lv]), S01[lv], ONE);
                        S23[lv-1] = fmul2(fmul2(TWO, S23[lv]), C23[lv]);
                        C23[lv-1] = ffma2(fmul2(NTWO, S23[lv]), S23[lv], ONE);
                    }
                    #pragma unroll 2
                    for (int j = 0; j < cnt; j++) {
                        ulonglong2 e0 = buf[j * 5 + 0];
                        ulonglong2 e1 = buf[j * 5 + 1];
                        ulonglong2 e2 = buf[j * 5 + 2];
                        ulonglong2 e3 = buf[j * 5 + 3];
                        ulonglong2 e4 = buf[j * 5 + 4];
                        ull r0 = ffma2(e0.y, T01, e0.x);
                        r0 = ffma2(e1.x, S01[0], r0); r0 = ffma2(e1.y, S01[1], r0);
                        r0 = ffma2(e2.x, S01[2], r0); r0 = ffma2(e2.y, S01[3], r0);
                        r0 = ffma2(e3.x, C01[0], r0); r0 = ffma2(e3.y, C01[1], r0);
                        r0 = ffma2(e4.x, C01[2], r0); r0 = ffma2(e4.y, C01[3], r0);
                        ull r1 = ffma2(e0.y, T23, e0.x);
                        r1 = ffma2(e1.x, S23[0], r1); r1 = ffma2(e1.y, S23[1], r1);
                        r1 = ffma2(e2.x, S23[2], r1); r1 = ffma2(e2.y, S23[3], r1);
                        r1 = ffma2(e3.x, C23[0], r1); r1 = ffma2(e3.y, C23[1], r1);
                        r1 = ffma2(e4.x, C23[2], r1); r1 = ffma2(e4.y, C23[3], r1);
                        longlong2 o;
                        o.x = (long long)r0; o.y = (long long)r1;
                        __stcs(reinterpret_cast<longlong2*>(
                                   out + (size_t)(gbase + j) * TT + t0), o);
                    }
                }
            }
        } else if (s + 1 < 3) {
            // WORK: gather+coef for sub-slab s+1 into the other buffer
            int tid2 = tid - 128;
            gather_coef(tid2, start + bb[s + 1], bb[s + 2] - bb[s + 1], ndA,
                        co, lt, amp, ph, lw, rw, li, ri, lab, s_cm, s_pp,
                        ((s + 1) & 1) ? s_cpB : s_cpA);
        }
    }
}

extern "C" void kernel_launch(void* const* d_in, const int* in_sizes, int n_in,
                              void* d_out, int out_size) {
    const float* tv  = (const float*)d_in[0];  // time_vector        [1000]
    const float* co  = (const float*)d_in[1];  // constant_offset    [50000]
    const float* lt  = (const float*)d_in[2];  // linear_trend       [50000]
    const float* amp = (const float*)d_in[3];  // seasonal_amplitudes[50000,4]
    const float* ph  = (const float*)d_in[4];  // seasonal_phases    [50000,4]
    const float* lw  = (const float*)d_in[5];  // local_w            [50000,5]
    const float* rw  = (const float*)d_in[6];  // regional_w         [50000,15]
    const int*   li  = (const int*)d_in[7];    // local_idx          [50000,5]
    const int*   ri  = (const int*)d_in[8];    // regional_idx       [50000,15]
    const int*   lab = (const int*)d_in[9];    // cluster_labels     [50000]
    float* out = (float*)d_out;

    k_pre<<<PREG, PRETHR>>>((const float4*)amp, (const float4*)ph, lab);
    k_fused<<<GRIDF, 256>>>(tv, co, lt, amp, ph, lw, rw, li, ri, lab, out);
}

// round 13
// speedup vs baseline: 1.0792x; 1.0792x over previous
#include <cuda_runtime.h>
#include <math.h>

#define NN 50000
#define TT 1000
#define KL 5
#define KR 15
#define NC 5
#define TWOPI 6.28318530717958647692f
#define PREG 148
#define PRETHR 512
#define GRIDF 592
#define MAXSLAB 85

typedef unsigned long long ull;

__device__ __forceinline__ ull pk2(float lo, float hi) {
    ull r; asm("mov.b64 %0,{%1,%2};" : "=l"(r) : "f"(lo), "f"(hi)); return r;
}
__device__ __forceinline__ ull ffma2(ull a, ull b, ull c) {
    ull d; asm("fma.rn.f32x2 %0,%1,%2,%3;" : "=l"(d) : "l"(a), "l"(b), "l"(c)); return d;
}

// per-block partial cluster sums: [count, sumAmp*4, sumCos*4, sumSin*4] x NC
__device__ float g_partial[PREG * 65];
// finalized cluster stats: [0..19] meanAmp, [20..39] circPhase, [40..44] big flag
__device__ float g_cmeans[48];
__device__ unsigned g_arr;  // arrival counter; reset by last block each launch

// ---------------------------------------------------------------------------
// Stage 1: cluster partial sums only (no node table — gather reads the raw
// inputs directly). 3-step warp butterfly; LAST block reduces to g_cmeans.
// Deterministic, replay-safe.
// ---------------------------------------------------------------------------
__global__ __launch_bounds__(PRETHR) void k_pre(const float4* __restrict__ amp,
                                                const float4* __restrict__ ph,
                                                const int* __restrict__ lab) {
    __shared__ float s_part[64 * 65];
    __shared__ float s_cl[65];
    __shared__ unsigned s_last;
    int tid = threadIdx.x;
    int wid = tid >> 5, lane = tid & 31;
    int n = blockIdx.x * PRETHR + tid;

    float v[13];
    int c = -1;
    if (n < NN) {
        float4 p = ph[n];
        float4 cs, sn;
        __sincosf(p.x, &sn.x, &cs.x);
        __sincosf(p.y, &sn.y, &cs.y);
        __sincosf(p.z, &sn.z, &cs.z);
        __sincosf(p.w, &sn.w, &cs.w);
        float4 a = amp[n];
        c = lab[n];
        v[0] = 1.f;
        v[1] = a.x;  v[2] = a.y;  v[3] = a.z;  v[4] = a.w;
        v[5] = cs.x; v[6] = cs.y; v[7] = cs.z; v[8] = cs.w;
        v[9] = sn.x; v[10] = sn.y; v[11] = sn.z; v[12] = sn.w;
    } else {
        #pragma unroll
        for (int i = 0; i < 13; i++) v[i] = 0.f;
    }

    #pragma unroll
    for (int cc = 0; cc < NC; cc++) {
        #pragma unroll
        for (int i = 0; i < 13; i++) {
            float x = (c == cc) ? v[i] : 0.f;
            x += __shfl_xor_sync(0xffffffffu, x, 16);
            x += __shfl_xor_sync(0xffffffffu, x, 8);
            x += __shfl_xor_sync(0xffffffffu, x, 4);
            if (lane < 4) s_part[(wid * 4 + lane) * 65 + cc * 13 + i] = x;
        }
    }
    __syncthreads();
    if (tid < 65) {
        float s = 0.f;
        #pragma unroll
        for (int w = 0; w < 64; w++) s += s_part[w * 65 + tid];
        g_partial[blockIdx.x * 65 + tid] = s;
    }
    __threadfence();
    __syncthreads();
    if (tid == 0) {
        unsigned o = atomicAdd(&g_arr, 1u);
        s_last = (o == PREG - 1) ? 1u : 0u;
    }
    __syncthreads();
    if (s_last) {
        __threadfence();
        if (tid < 65) {
            float s = 0.f;
            for (int r = 0; r < PREG; r++) s += g_partial[r * 65 + tid];
            s_cl[tid] = s;
        }
        __syncthreads();
        if (tid < 20) {
            int cc = tid >> 2, i = tid & 3;
            float cnt = s_cl[cc * 13];
            g_cmeans[tid]      = s_cl[cc * 13 + 1 + i] / fmaxf(cnt, 1.f);
            g_cmeans[20 + tid] = atan2f(s_cl[cc * 13 + 9 + i], s_cl[cc * 13 + 5 + i]);
            if (i == 0) g_cmeans[40 + cc] = (cnt > 1.f) ? 1.f : 0.f;
        }
        if (tid == 0) g_arr = 0u;   // reset for next graph replay
    }
}

// ---------------------------------------------------------------------------
// Stage 2 (fused coef + fill), R7 structure. Block b owns slab of <=85 nodes.
//   phase A: 3 threads/node gather straight from amp[]/ph[] (2 LDG.128 per
//            neighbor, L2-resident 1.6MB) with on-the-fly __sincosf.
//   phase B: owner thread merges partials -> dup-packed coefficients.
//   phase C: 250 threads x 4 t fill, f32x2 FMA chain, streaming stores.
// ---------------------------------------------------------------------------
__global__ __launch_bounds__(256, 4) void k_fused(const float* __restrict__ tv,
                                                  const float* __restrict__ co,
                                                  const float* __restrict__ lt,
                                                  const float* __restrict__ amp,
                                                  const float* __restrict__ ph,
                                                  const float* __restrict__ lw,
                                                  const float* __restrict__ rw,
                                                  const int* __restrict__ li,
                                                  const int* __restrict__ ri,
                                                  const int* __restrict__ lab,
                                                  float* __restrict__ out) {
    __shared__ float s_cm[48];
    __shared__ float s_pp[MAXSLAB * 24];     // chunk1: [0..11], chunk2: [12..23]
    __shared__ ulonglong2 s_cp[MAXSLAB * 5]; // dup-packed coefficients
    int tid = threadIdx.x;
    int start = (int)(((long long)blockIdx.x * NN) / GRIDF);
    int end   = (int)(((long long)(blockIdx.x + 1) * NN) / GRIDF);
    int nn = end - start;

    if (tid < 48) s_cm[tid] = g_cmeans[tid];

    int node = -1, chunk = 0;
    if (tid < nn)          { node = tid;          chunk = 0; }
    else if (tid < 2 * nn) { node = tid - nn;     chunk = 1; }
    else if (tid < 3 * nn) { node = tid - 2 * nn; chunk = 2; }

    const float4* ampP = (const float4*)amp;
    const float4* phP  = (const float4*)ph;

    // owner-persistent state (chunk 0)
    float la[4] = {0,0,0,0}, lc[4] = {0,0,0,0}, ls[4] = {0,0,0,0};
    float4 a4, p4;
    float cov = 0.f, ltv = 0.f;
    int c = 0;

    if (node >= 0) {
        int gn = start + node;
        if (chunk == 0) {
            a4 = ampP[gn];
            p4 = phP[gn];
            cov = co[gn]; ltv = lt[gn]; c = lab[gn];
            #pragma unroll
            for (int k = 0; k < KL; k++) {
                int j = li[gn * KL + k];
                float w = lw[gn * KL + k];
                float4 aj = ampP[j];
                float4 pj = phP[j];
                float c0, s0, c1, s1, c2, s2, c3, s3;
                __sincosf(pj.x, &s0, &c0);
                __sincosf(pj.y, &s1, &c1);
                __sincosf(pj.z, &s2, &c2);
                __sincosf(pj.w, &s3, &c3);
                la[0] = fmaf(aj.x, w, la[0]); la[1] = fmaf(aj.y, w, la[1]);
                la[2] = fmaf(aj.z, w, la[2]); la[3] = fmaf(aj.w, w, la[3]);
                lc[0] = fmaf(c0, w, lc[0]); lc[1] = fmaf(c1, w, lc[1]);
                lc[2] = fmaf(c2, w, lc[2]); lc[3] = fmaf(c3, w, lc[3]);
                ls[0] = fmaf(s0, w, ls[0]); ls[1] = fmaf(s1, w, ls[1]);
                ls[2] = fmaf(s2, w, ls[2]); ls[3] = fmaf(s3, w, ls[3]);
            }
        } else {
            int kb = (chunk == 1) ? 0 : 8;
            int ke = (chunk == 1) ? 8 : KR;
            float sa[4] = {0,0,0,0}, sc[4] = {0,0,0,0}, ss[4] = {0,0,0,0};
            for (int k = kb; k < ke; k++) {
                int j = ri[gn * KR + k];
                float w = rw[gn * KR + k];
                float4 aj = ampP[j];
                float4 pj = phP[j];
                float c0, s0, c1, s1, c2, s2, c3, s3;
                __sincosf(pj.x, &s0, &c0);
                __sincosf(pj.y, &s1, &c1);
                __sincosf(pj.z, &s2, &c2);
                __sincosf(pj.w, &s3, &c3);
                sa[0] = fmaf(aj.x, w, sa[0]); sa[1] = fmaf(aj.y, w, sa[1]);
                sa[2] = fmaf(aj.z, w, sa[2]); sa[3] = fmaf(aj.w, w, sa[3]);
                sc[0] = fmaf(c0, w, sc[0]); sc[1] = fmaf(c1, w, sc[1]);
                sc[2] = fmaf(c2, w, sc[2]); sc[3] = fmaf(c3, w, sc[3]);
                ss[0] = fmaf(s0, w, ss[0]); ss[1] = fmaf(s1, w, ss[1]);
                ss[2] = fmaf(s2, w, ss[2]); ss[3] = fmaf(s3, w, ss[3]);
            }
            float* dst = &s_pp[node * 24 + (chunk - 1) * 12];
            #pragma unroll
            for (int i = 0; i < 4; i++) {
                dst[i] = sa[i]; dst[4 + i] = sc[i]; dst[8 + i] = ss[i];
            }
        }
    }
    __syncthreads();

    if (node >= 0 && chunk == 0) {
        const float* p1 = &s_pp[node * 24];
        const float* p2 = p1 + 12;
        bool big = s_cm[40 + c] > 0.5f;
        float aP[4] = {a4.x, a4.y, a4.z, a4.w};
        float pP[4] = {p4.x, p4.y, p4.z, p4.w};
        float av[4], bv[4];
        #pragma unroll
        for (int i = 0; i < 4; i++) {
            float ra = p1[i] + p2[i];
            float rc = p1[4 + i] + p2[4 + i];
            float rs = p1[8 + i] + p2[8 + i];
            float campU = big ? s_cm[c * 4 + i] : aP[i];
            // combined = 0.5*local + 0.3*(0.7*regional_sum) + 0.2*cluster
            float ampO = 0.7f * aP[i] + 0.3f * (0.5f * la[i] + 0.21f * ra + 0.2f * campU);
            float cphU = big ? s_cm[20 + c * 4 + i] : pP[i];
            float phL = atan2f(ls[i], lc[i]);
            float phR = atan2f(rs, rc);
            float phO = 0.7f * pP[i] + 0.3f * (0.5f * phL + 0.3f * phR + 0.2f * cphU);
            float s, cc2;
            __sincosf(phO, &s, &cc2);
            av[i] = ampO * cc2;
            bv[i] = ampO * s;
        }
        ull* q = (ull*)&s_cp[node * 5];
        q[0] = pk2(cov, cov);     q[1] = pk2(ltv, ltv);
        q[2] = pk2(av[0], av[0]); q[3] = pk2(av[1], av[1]);
        q[4] = pk2(av[2], av[2]); q[5] = pk2(av[3], av[3]);
        q[6] = pk2(bv[0], bv[0]); q[7] = pk2(bv[1], bv[1]);
        q[8] = pk2(bv[2], bv[2]); q[9] = pk2(bv[3], bv[3]);
    }
    __syncthreads();

    int t0 = tid * 4;
    if (t0 >= TT) return;  // threads 250..255 already did their shared-memory duty

    float4 tvv = ((const float4*)tv)[tid];
    ull T01 = pk2(tvv.x, tvv.y);
    ull T23 = pk2(tvv.z, tvv.w);

    const float w[4] = {TWOPI * 4.f, TWOPI * 2.f, TWOPI, TWOPI * 0.5f};
    ull S01[4], C01[4], S23[4], C23[4];
    #pragma unroll
    for (int i = 0; i < 4; i++) {
        float s0, c0, s1, c1, s2, c2, s3, c3;
        sincosf(w[i] * tvv.x, &s0, &c0);
        sincosf(w[i] * tvv.y, &s1, &c1);
        sincosf(w[i] * tvv.z, &s2, &c2);
        sincosf(w[i] * tvv.w, &s3, &c3);
        S01[i] = pk2(s0, s1); C01[i] = pk2(c0, c1);
        S23[i] = pk2(s2, s3); C23[i] = pk2(c2, c3);
    }

    #pragma unroll 2
    for (int j = 0; j < nn; j++) {
        ulonglong2 e0 = s_cp[j * 5 + 0];
        ulonglong2 e1 = s_cp[j * 5 + 1];
        ulonglong2 e2 = s_cp[j * 5 + 2];
        ulonglong2 e3 = s_cp[j * 5 + 3];
        ulonglong2 e4 = s_cp[j * 5 + 4];
        ull r0 = ffma2(e0.y, T01, e0.x);
        r0 = ffma2(e1.x, S01[0], r0); r0 = ffma2(e1.y, S01[1], r0);
        r0 = ffma2(e2.x, S01[2], r0); r0 = ffma2(e2.y, S01[3], r0);
        r0 = ffma2(e3.x, C01[0], r0); r0 = ffma2(e3.y, C01[1], r0);
        r0 = ffma2(e4.x, C01[2], r0); r0 = ffma2(e4.y, C01[3], r0);
        ull r1 = ffma2(e0.y, T23, e0.x);
        r1 = ffma2(e1.x, S23[0], r1); r1 = ffma2(e1.y, S23[1], r1);
        r1 = ffma2(e2.x, S23[2], r1); r1 = ffma2(e2.y, S23[3], r1);
        r1 = ffma2(e3.x, C23[0], r1); r1 = ffma2(e3.y, C23[1], r1);
        r1 = ffma2(e4.x, C23[2], r1); r1 = ffma2(e4.y, C23[3], r1);
        longlong2 o;
        o.x = (long long)r0; o.y = (long long)r1;
        __stcs(reinterpret_cast<longlong2*>(out + (size_t)(start + j) * TT + t0), o);
    }
}

extern "C" void kernel_launch(void* const* d_in, const int* in_sizes, int n_in,
                              void* d_out, int out_size) {
    const float* tv  = (const float*)d_in[0];  // time_vector        [1000]
    const float* co  = (const float*)d_in[1];  // constant_offset    [50000]
    const float* lt  = (const float*)d_in[2];  // linear_trend       [50000]
    const float* amp = (const float*)d_in[3];  // seasonal_amplitudes[50000,4]
    const float* ph  = (const float*)d_in[4];  // seasonal_phases    [50000,4]
    const float* lw  = (const float*)d_in[5];  // local_w            [50000,5]
    const float* rw  = (const float*)d_in[6];  // regional_w         [50000,15]
    const int*   li  = (const int*)d_in[7];    // local_idx          [50000,5]
    const int*   ri  = (const int*)d_in[8];    // regional_idx       [50000,15]
    const int*   lab = (const int*)d_in[9];    // cluster_labels     [50000]
    float* out = (float*)d_out;

    k_pre<<<PREG, PRETHR>>>((const float4*)amp, (const float4*)ph, lab);
    k_fused<<<GRIDF, 256>>>(tv, co, lt, amp, ph, lw, rw, li, ri, lab, out);
}

// round 14
// speedup vs baseline: 1.0951x; 1.0147x over previous
#include <cuda_runtime.h>
#include <math.h>

#define NN 50000
#define TT 1000
#define KL 5
#define KR 15
#define NC 5
#define TWOPI 6.28318530717958647692f
#define PREG 148
#define PRETHR 512
#define GRIDF 444
#define MAXSLAB 113

typedef unsigned long long ull;

__device__ __forceinline__ ull pk2(float lo, float hi) {
    ull r; asm("mov.b64 %0,{%1,%2};" : "=l"(r) : "f"(lo), "f"(hi)); return r;
}
__device__ __forceinline__ ull ffma2(ull a, ull b, ull c) {
    ull d; asm("fma.rn.f32x2 %0,%1,%2,%3;" : "=l"(d) : "l"(a), "l"(b), "l"(c)); return d;
}

// per-block partial cluster sums: [count, sumAmp*4, sumCos*4, sumSin*4] x NC
__device__ float g_partial[PREG * 65];
// finalized cluster stats: [0..19] meanAmp, [20..39] circPhase, [40..44] big flag
__device__ float g_cmeans[48];
__device__ unsigned g_arr;  // arrival counter; reset by last block each launch

// ---------------------------------------------------------------------------
// Stage 1 (unchanged, verified): cluster partial sums; last block finalizes.
// ---------------------------------------------------------------------------
__global__ __launch_bounds__(PRETHR) void k_pre(const float4* __restrict__ amp,
                                                const float4* __restrict__ ph,
                                                const int* __restrict__ lab) {
    __shared__ float s_part[64 * 65];
    __shared__ float s_cl[65];
    __shared__ unsigned s_last;
    int tid = threadIdx.x;
    int wid = tid >> 5, lane = tid & 31;
    int n = blockIdx.x * PRETHR + tid;

    float v[13];
    int c = -1;
    if (n < NN) {
        float4 p = ph[n];
        float4 cs, sn;
        __sincosf(p.x, &sn.x, &cs.x);
        __sincosf(p.y, &sn.y, &cs.y);
        __sincosf(p.z, &sn.z, &cs.z);
        __sincosf(p.w, &sn.w, &cs.w);
        float4 a = amp[n];
        c = lab[n];
        v[0] = 1.f;
        v[1] = a.x;  v[2] = a.y;  v[3] = a.z;  v[4] = a.w;
        v[5] = cs.x; v[6] = cs.y; v[7] = cs.z; v[8] = cs.w;
        v[9] = sn.x; v[10] = sn.y; v[11] = sn.z; v[12] = sn.w;
    } else {
        #pragma unroll
        for (int i = 0; i < 13; i++) v[i] = 0.f;
    }

    #pragma unroll
    for (int cc = 0; cc < NC; cc++) {
        #pragma unroll
        for (int i = 0; i < 13; i++) {
            float x = (c == cc) ? v[i] : 0.f;
            x += __shfl_xor_sync(0xffffffffu, x, 16);
            x += __shfl_xor_sync(0xffffffffu, x, 8);
            x += __shfl_xor_sync(0xffffffffu, x, 4);
            if (lane < 4) s_part[(wid * 4 + lane) * 65 + cc * 13 + i] = x;
        }
    }
    __syncthreads();
    if (tid < 65) {
        float s = 0.f;
        #pragma unroll
        for (int w = 0; w < 64; w++) s += s_part[w * 65 + tid];
        g_partial[blockIdx.x * 65 + tid] = s;
    }
    __threadfence();
    __syncthreads();
    if (tid == 0) {
        unsigned o = atomicAdd(&g_arr, 1u);
        s_last = (o == PREG - 1) ? 1u : 0u;
    }
    __syncthreads();
    if (s_last) {
        __threadfence();
        if (tid < 65) {
            float s = 0.f;
            for (int r = 0; r < PREG; r++) s += g_partial[r * 65 + tid];
            s_cl[tid] = s;
        }
        __syncthreads();
        if (tid < 20) {
            int cc = tid >> 2, i = tid & 3;
            float cnt = s_cl[cc * 13];
            g_cmeans[tid]      = s_cl[cc * 13 + 1 + i] / fmaxf(cnt, 1.f);
            g_cmeans[20 + tid] = atan2f(s_cl[cc * 13 + 9 + i], s_cl[cc * 13 + 5 + i]);
            if (i == 0) g_cmeans[40 + cc] = (cnt > 1.f) ? 1.f : 0.f;
        }
        if (tid == 0) g_arr = 0u;   // reset for next graph replay
    }
}

// Accumulate up to 4 neighbors with BATCHED loads (8 LDG.128 issued together
// -> one L2 round trip per group instead of four).
__device__ __forceinline__ void accum4(const float4* __restrict__ ampP,
                                       const float4* __restrict__ phP,
                                       const int* jj, const float* ww, int cnt,
                                       float* sa, float* sc, float* ss) {
    float4 aj[4], pj[4];
    #pragma unroll
    for (int k = 0; k < 4; k++) {
        if (k < cnt) { aj[k] = ampP[jj[k]]; pj[k] = phP[jj[k]]; }
    }
    #pragma unroll
    for (int k = 0; k < 4; k++) {
        if (k < cnt) {
            float w = ww[k];
            float c0, s0, c1, s1, c2, s2, c3, s3;
            __sincosf(pj[k].x, &s0, &c0);
            __sincosf(pj[k].y, &s1, &c1);
            __sincosf(pj[k].z, &s2, &c2);
            __sincosf(pj[k].w, &s3, &c3);
            sa[0] = fmaf(aj[k].x, w, sa[0]); sa[1] = fmaf(aj[k].y, w, sa[1]);
            sa[2] = fmaf(aj[k].z, w, sa[2]); sa[3] = fmaf(aj[k].w, w, sa[3]);
            sc[0] = fmaf(c0, w, sc[0]); sc[1] = fmaf(c1, w, sc[1]);
            sc[2] = fmaf(c2, w, sc[2]); sc[3] = fmaf(c3, w, sc[3]);
            ss[0] = fmaf(s0, w, ss[0]); ss[1] = fmaf(s1, w, ss[1]);
            ss[2] = fmaf(s2, w, ss[2]); ss[3] = fmaf(s3, w, ss[3]);
        }
    }
}

// ---------------------------------------------------------------------------
// Stage 2 (fused coef + fill). 3 blocks/SM (more regs -> gather MLP).
//   phase A: role loop, 3 roles/node, batched neighbor loads -> s_pp.
//   phase B: per node: merge partials, atan2/sincos -> dup-packed coeffs.
//   phase C: 250 threads x 4 t fill, f32x2 chain, streaming stores.
// ---------------------------------------------------------------------------
__global__ __launch_bounds__(256, 3) void k_fused(const float* __restrict__ tv,
                                                  const float* __restrict__ co,
                                                  const float* __restrict__ lt,
                                                  const float* __restrict__ amp,
                                                  const float* __restrict__ ph,
                                                  const float* __restrict__ lw,
                                                  const float* __restrict__ rw,
                                                  const int* __restrict__ li,
                                                  const int* __restrict__ ri,
                                                  const int* __restrict__ lab,
                                                  float* __restrict__ out) {
    __shared__ float s_cm[48];
    __shared__ float s_pp[MAXSLAB * 36];     // 3 chunks x 12 floats per node
    __shared__ ulonglong2 s_cp[MAXSLAB * 5]; // dup-packed coefficients
    int tid = threadIdx.x;
    int start = (int)(((long long)blockIdx.x * NN) / GRIDF);
    int end   = (int)(((long long)(blockIdx.x + 1) * NN) / GRIDF);
    int nn = end - start;

    if (tid < 48) s_cm[tid] = g_cmeans[tid];

    const float4* ampP = (const float4*)amp;
    const float4* phP  = (const float4*)ph;

    // phase A: gather, 3 roles per node (local | regional 0-7 | regional 8-14)
    for (int i = tid; i < 3 * nn; i += 256) {
        int chunk = i / nn, node = i - chunk * nn;
        int gn = start + node;
        float sa[4] = {0,0,0,0}, sc[4] = {0,0,0,0}, ss[4] = {0,0,0,0};
        if (chunk == 0) {
            int jj[5]; float ww[5];
            #pragma unroll
            for (int k = 0; k < KL; k++) {
                jj[k] = li[gn * KL + k];
                ww[k] = lw[gn * KL + k];
            }
            accum4(ampP, phP, jj, ww, 4, sa, sc, ss);
            accum4(ampP, phP, jj + 4, ww + 4, 1, sa, sc, ss);
        } else {
            int kb = (chunk == 1) ? 0 : 8;
            int cntk = (chunk == 1) ? 8 : 7;
            int jj[8]; float ww[8];
            #pragma unroll
            for (int k = 0; k < 8; k++) {
                if (k < cntk) {
                    jj[k] = ri[gn * KR + kb + k];
                    ww[k] = rw[gn * KR + kb + k];
                }
            }
            accum4(ampP, phP, jj, ww, 4, sa, sc, ss);
            accum4(ampP, phP, jj + 4, ww + 4, cntk - 4, sa, sc, ss);
        }
        float* dst = &s_pp[node * 36 + chunk * 12];
        #pragma unroll
        for (int k = 0; k < 4; k++) {
            dst[k] = sa[k]; dst[4 + k] = sc[k]; dst[8 + k] = ss[k];
        }
    }
    __syncthreads();

    // phase B: coefficients
    for (int node = tid; node < nn; node += 256) {
        int gn = start + node;
        const float* p0 = &s_pp[node * 36];
        const float* p1 = p0 + 12;
        const float* p2 = p0 + 24;
        float4 a4 = ampP[gn];
        float4 p4 = phP[gn];
        float cov = co[gn], ltv = lt[gn];
        int c = lab[gn];
        bool big = s_cm[40 + c] > 0.5f;
        float aP[4] = {a4.x, a4.y, a4.z, a4.w};
        float pP[4] = {p4.x, p4.y, p4.z, p4.w};
        float av[4], bv[4];
        #pragma unroll
        for (int i = 0; i < 4; i++) {
            float ra = p1[i] + p2[i];
            float rc = p1[4 + i] + p2[4 + i];
            float rs = p1[8 + i] + p2[8 + i];
            float campU = big ? s_cm[c * 4 + i] : aP[i];
            // combined = 0.5*local + 0.3*(0.7*regional_sum) + 0.2*cluster
            float ampO = 0.7f * aP[i] + 0.3f * (0.5f * p0[i] + 0.21f * ra + 0.2f * campU);
            float cphU = big ? s_cm[20 + c * 4 + i] : pP[i];
            float phL = atan2f(p0[8 + i], p0[4 + i]);
            float phR = atan2f(rs, rc);
            float phO = 0.7f * pP[i] + 0.3f * (0.5f * phL + 0.3f * phR + 0.2f * cphU);
            float s, cc2;
            __sincosf(phO, &s, &cc2);
            av[i] = ampO * cc2;
            bv[i] = ampO * s;
        }
        ull* q = (ull*)&s_cp[node * 5];
        q[0] = pk2(cov, cov);     q[1] = pk2(ltv, ltv);
        q[2] = pk2(av[0], av[0]); q[3] = pk2(av[1], av[1]);
        q[4] = pk2(av[2], av[2]); q[5] = pk2(av[3], av[3]);
        q[6] = pk2(bv[0], bv[0]); q[7] = pk2(bv[1], bv[1]);
        q[8] = pk2(bv[2], bv[2]); q[9] = pk2(bv[3], bv[3]);
    }
    __syncthreads();

    int t0 = tid * 4;
    if (t0 >= TT) return;  // threads 250..255 already did their shared-memory duty

    float4 tvv = ((const float4*)tv)[tid];
    ull T01 = pk2(tvv.x, tvv.y);
    ull T23 = pk2(tvv.z, tvv.w);

    const float w[4] = {TWOPI * 4.f, TWOPI * 2.f, TWOPI, TWOPI * 0.5f};
    ull S01[4], C01[4], S23[4], C23[4];
    #pragma unroll
    for (int i = 0; i < 4; i++) {
        float s0, c0, s1, c1, s2, c2, s3, c3;
        sincosf(w[i] * tvv.x, &s0, &c0);
        sincosf(w[i] * tvv.y, &s1, &c1);
        sincosf(w[i] * tvv.z, &s2, &c2);
        sincosf(w[i] * tvv.w, &s3, &c3);
        S01[i] = pk2(s0, s1); C01[i] = pk2(c0, c1);
        S23[i] = pk2(s2, s3); C23[i] = pk2(c2, c3);
    }

    #pragma unroll 2
    for (int j = 0; j < nn; j++) {
        ulonglong2 e0 = s_cp[j * 5 + 0];
        ulonglong2 e1 = s_cp[j * 5 + 1];
        ulonglong2 e2 = s_cp[j * 5 + 2];
        ulonglong2 e3 = s_cp[j * 5 + 3];
        ulonglong2 e4 = s_cp[j * 5 + 4];
        ull r0 = ffma2(e0.y, T01, e0.x);
        r0 = ffma2(e1.x, S01[0], r0); r0 = ffma2(e1.y, S01[1], r0);
        r0 = ffma2(e2.x, S01[2], r0); r0 = ffma2(e2.y, S01[3], r0);
        r0 = ffma2(e3.x, C01[0], r0); r0 = ffma2(e3.y, C01[1], r0);
        r0 = ffma2(e4.x, C01[2], r0); r0 = ffma2(e4.y, C01[3], r0);
        ull r1 = ffma2(e0.y, T23, e0.x);
        r1 = ffma2(e1.x, S23[0], r1); r1 = ffma2(e1.y, S23[1], r1);
        r1 = ffma2(e2.x, S23[2], r1); r1 = ffma2(e2.y, S23[3], r1);
        r1 = ffma2(e3.x, C23[0], r1); r1 = ffma2(e3.y, C23[1], r1);
        r1 = ffma2(e4.x, C23[2], r1); r1 = ffma2(e4.y, C23[3], r1);
        longlong2 o;
        o.x = (long long)r0; o.y = (long long)r1;
        __stcs(reinterpret_cast<longlong2*>(out + (size_t)(start + j) * TT + t0), o);
    }
}

extern "C" void kernel_launch(void* const* d_in, const int* in_sizes, int n_in,
                              void* d_out, int out_size) {
    const float* tv  = (const float*)d_in[0];  // time_vector        [1000]
    const float* co  = (const float*)d_in[1];  // constant_offset    [50000]
    const float* lt  = (const float*)d_in[2];  // linear_trend       [50000]
    const float* amp = (const float*)d_in[3];  // seasonal_amplitudes[50000,4]
    const float* ph  = (const float*)d_in[4];  // seasonal_phases    [50000,4]
    const float* lw  = (const float*)d_in[5];  // local_w            [50000,5]
    const float* rw  = (const float*)d_in[6];  // regional_w         [50000,15]
    const int*   li  = (const int*)d_in[7];    // local_idx          [50000,5]
    const int*   ri  = (const int*)d_in[8];    // regional_idx       [50000,15]
    const int*   lab = (const int*)d_in[9];    // cluster_labels     [50000]
    float* out = (float*)d_out;

    k_pre<<<PREG, PRETHR>>>((const float4*)amp, (const float4*)ph, lab);
    k_fused<<<GRIDF, 256>>>(tv, co, lt, amp, ph, lw, rw, li, ri, lab, out);
}